// round 3
// baseline (speedup 1.0000x reference)
#include <cuda_runtime.h>

// NeighborhoodAggregation: out = (segment_sum(Z[src], dst) + Z) / counts  (self-loop + degree-normalize)
// Inputs (metadata order): Z_real (100000*64 f32), Z_imag (100000*64 f32),
//                          edge_index (2*1600000, int32 per harness dtype normalization)
// Output: float32, [A_real (100000*64) ; A_imag (100000*64)]

#define MAX_NODES 100000

__device__ float g_counts[MAX_NODES];

// Kernel 1: implement self-loop by initializing out = Z, counts = 1
__global__ void init_kernel(const float4* __restrict__ zr,
                            const float4* __restrict__ zi,
                            float4* __restrict__ outr,
                            float4* __restrict__ outi,
                            int n_nodes)
{
    int i = blockIdx.x * blockDim.x + threadIdx.x;
    int total = n_nodes * 16;  // 64 floats = 16 float4 per row
    if (i < total) {
        outr[i] = zr[i];
        outi[i] = zi[i];
    }
    if (i < n_nodes) {
        g_counts[i] = 1.0f;
    }
}

// Kernel 2: scatter-add edges. 16 threads per edge; each thread handles one
// float4 chunk of the 64-wide feature row for both real and imag parts,
// using vectorized float4 atomics (RED.ADD.F32.V4 on sm_90+).
__global__ void edge_kernel(const int* __restrict__ src,
                            const int* __restrict__ dst,
                            const float4* __restrict__ zr,
                            const float4* __restrict__ zi,
                            float4* __restrict__ outr,
                            float4* __restrict__ outi,
                            int n_edges)
{
    long long t = (long long)blockIdx.x * blockDim.x + threadIdx.x;
    int e = (int)(t >> 4);
    int j = (int)(t & 15);
    if (e >= n_edges) return;

    int s = src[e];
    int d = dst[e];

    float4 vr = zr[(size_t)s * 16 + j];
    float4 vi = zi[(size_t)s * 16 + j];

#if __CUDA_ARCH__ >= 900
    atomicAdd(&outr[(size_t)d * 16 + j], vr);
    atomicAdd(&outi[(size_t)d * 16 + j], vi);
#else
    float* pr = (float*)&outr[(size_t)d * 16 + j];
    atomicAdd(pr + 0, vr.x);
    atomicAdd(pr + 1, vr.y);
    atomicAdd(pr + 2, vr.z);
    atomicAdd(pr + 3, vr.w);
    float* pi = (float*)&outi[(size_t)d * 16 + j];
    atomicAdd(pi + 0, vi.x);
    atomicAdd(pi + 1, vi.y);
    atomicAdd(pi + 2, vi.z);
    atomicAdd(pi + 3, vi.w);
#endif

    if (j == 0) {
        atomicAdd(&g_counts[d], 1.0f);
    }
}

// Kernel 3: normalize by counts (counts >= 1 guaranteed by self-loop)
__global__ void norm_kernel(float4* __restrict__ outr,
                            float4* __restrict__ outi,
                            int n_nodes)
{
    int i = blockIdx.x * blockDim.x + threadIdx.x;
    int total = n_nodes * 16;
    if (i >= total) return;
    float inv = 1.0f / g_counts[i >> 4];
    float4 r = outr[i];
    r.x *= inv; r.y *= inv; r.z *= inv; r.w *= inv;
    outr[i] = r;
    float4 m = outi[i];
    m.x *= inv; m.y *= inv; m.z *= inv; m.w *= inv;
    outi[i] = m;
}

extern "C" void kernel_launch(void* const* d_in, const int* in_sizes, int n_in,
                              void* d_out, int out_size)
{
    const float* Z_real = (const float*)d_in[0];
    const float* Z_imag = (const float*)d_in[1];
    const int* edge_index = (const int*)d_in[2];

    int n_nodes = in_sizes[0] / 64;
    int n_edges = in_sizes[2] / 2;

    const int* src = edge_index;
    const int* dst = edge_index + n_edges;

    float* out_real = (float*)d_out;
    float* out_imag = (float*)d_out + (size_t)n_nodes * 64;

    // Kernel 1: init (self-loop copy + counts = 1)
    {
        int total = n_nodes * 16;
        int threads = 256;
        int blocks = (total + threads - 1) / threads;
        init_kernel<<<blocks, threads>>>((const float4*)Z_real, (const float4*)Z_imag,
                                         (float4*)out_real, (float4*)out_imag, n_nodes);
    }

    // Kernel 2: edge scatter-add
    {
        long long total = (long long)n_edges * 16;
        int threads = 256;
        long long blocks = (total + threads - 1) / threads;
        edge_kernel<<<(unsigned)blocks, threads>>>(src, dst,
                                                   (const float4*)Z_real, (const float4*)Z_imag,
                                                   (float4*)out_real, (float4*)out_imag, n_edges);
    }

    // Kernel 3: normalize
    {
        int total = n_nodes * 16;
        int threads = 256;
        int blocks = (total + threads - 1) / threads;
        norm_kernel<<<blocks, threads>>>((float4*)out_real, (float4*)out_imag, n_nodes);
    }
}